// round 16
// baseline (speedup 1.0000x reference)
#include <cuda_runtime.h>
#include <cuda_fp16.h>
#include <math.h>
#include <stdint.h>

#define Bn  128
#define Ln  577
#define LP  640
#define Dn  768
#define NPn 1024
#define EPSF 1e-8f
#define STAGE_B 49152
#define SMEM_MMA1 (2 * STAGE_B)
#define SMEM_MMA2 (2 * STAGE_B + 2560)

// ---------------- device scratch ----------------
__device__ __half g_Yt [(size_t)Bn*NPn*LP];   // y = leaky(S), [b][n][l]; pads stay 0
__device__ __half g_tok[(size_t)Bn*Ln*Dn];    // tokens fp16, [b][l][d]
__device__ __half g_npf[NPn*Dn];
__device__ __half g_img[Bn*Dn];
__device__ __half g_txt[Bn*Dn];
__device__ float  g_norm2[Bn*Ln];
__device__ float  g_qn  [NPn];
__device__ float  g_num [Bn*NPn];
__device__ float  g_wn2 [Bn*NPn];
__device__ float  g_ct  [Bn*Bn];
__device__ float  g_npc [Bn*NPn];
__device__ float  g_acc;
__device__ int    g_lcnt;
__device__ int    g_idx64;

__device__ __forceinline__ float lk(float x) { return x >= 0.f ? x : 0.1f * x; }
__device__ __forceinline__ float logsig(float x) {
    return fminf(x, 0.f) - log1pf(expf(-fabsf(x)));
}
__device__ __forceinline__ uint32_t s2u(const void* p) {
    uint32_t a;
    asm("{ .reg .u64 t; cvta.to.shared.u64 t, %1; cvt.u32.u64 %0, t; }" : "=r"(a) : "l"(p));
    return a;
}

// -------- cp.async K-major tile: ROWS x 64 halfs, SW128 swizzle ---------------
template<int ROWS>
__device__ __forceinline__ void cpa_tile(uint32_t dst, const __half* __restrict__ src,
                                         int row0, int row_lim, size_t stride, int k0, int tid) {
#pragma unroll
    for (int i = 0; i < ROWS / 32; i++) {
        int e = tid + (i << 8);
        int r = e >> 3, c = e & 7;
        int gr = row0 + r;
        int sz = 16;
        if (gr >= row_lim) { gr = row_lim - 1; sz = 0; }
        const void* gp = (const void*)(src + (size_t)gr * stride + k0 + (c << 3));
        uint32_t off = (uint32_t)((r << 7) + (c << 4));
        off ^= (off >> 3) & 0x70;
        asm volatile("cp.async.cg.shared.global [%0], [%1], 16, %2;"
                     :: "r"(dst + off), "l"(gp), "r"(sz) : "memory");
    }
}
// -------- cp.async MN-major tile: 64 rows(l) x 256 halfs(d), 4-bit row XOR ----
__device__ __forceinline__ void cpa_tile_tr(uint32_t dst, const __half* __restrict__ src,
                                            int row0, int row_lim, size_t stride, int tid) {
#pragma unroll
    for (int i = 0; i < 8; i++) {
        int e = tid + (i << 8);
        int r = e >> 5, c = e & 31;
        int gr = row0 + r;
        int sz = 16;
        if (gr >= row_lim) { gr = row_lim - 1; sz = 0; }
        const void* gp = (const void*)(src + (size_t)gr * stride + (c << 3));
        uint32_t phys = (uint32_t)(r << 9) + ((uint32_t)(c << 4) ^ ((uint32_t)(r & 15) << 4));
        asm volatile("cp.async.cg.shared.global [%0], [%1], 16, %2;"
                     :: "r"(dst + phys), "l"(gp), "r"(sz) : "memory");
    }
}
#define CPA_COMMIT() asm volatile("cp.async.commit_group;" ::: "memory")

// ---------------- warp MMA (f16 acc) over one 128x256x64 SMEM chunk ------------
template<bool TRANSB>
__device__ __forceinline__ void mma_compute(uint32_t aBase, uint32_t bBase,
                                            int lane, int warpM, int warpN,
                                            uint32_t (&acc)[4][8][2]) {
#pragma unroll
    for (int ks = 0; ks < 4; ks++) {
        uint32_t a[4][4];
#pragma unroll
        for (int mb = 0; mb < 4; mb++) {
            int row = warpM * 64 + mb * 16 + (lane & 15);
            uint32_t byte = (uint32_t)(ks * 32 + ((lane >> 4) << 4));
            uint32_t off = (uint32_t)(row << 7) + byte;
            off ^= (off >> 3) & 0x70;
            asm volatile("ldmatrix.sync.aligned.m8n8.x4.shared.b16 {%0,%1,%2,%3}, [%4];"
                         : "=r"(a[mb][0]), "=r"(a[mb][1]), "=r"(a[mb][2]), "=r"(a[mb][3])
                         : "r"(aBase + off));
        }
        uint32_t b[8][2];
        if (!TRANSB) {
#pragma unroll
            for (int g = 0; g < 4; g++) {
                int row = warpN * 64 + g * 16 + (lane & 7) + ((lane >> 4) << 3);
                uint32_t byte = (uint32_t)(ks * 32 + ((lane & 8) ? 16 : 0));
                uint32_t off = (uint32_t)(row << 7) + byte;
                off ^= (off >> 3) & 0x70;
                uint32_t r0, r1, r2, r3;
                asm volatile("ldmatrix.sync.aligned.m8n8.x4.shared.b16 {%0,%1,%2,%3}, [%4];"
                             : "=r"(r0), "=r"(r1), "=r"(r2), "=r"(r3)
                             : "r"(bBase + off));
                b[g * 2][0] = r0; b[g * 2][1] = r1;
                b[g * 2 + 1][0] = r2; b[g * 2 + 1][1] = r3;
            }
        } else {
#pragma unroll
            for (int g = 0; g < 4; g++) {
                int row = ks * 16 + (lane & 15);
                uint32_t bir = (uint32_t)(warpN * 128 + g * 32 + ((lane >> 4) << 4));
                uint32_t phys = (uint32_t)(row << 9) + (bir ^ ((uint32_t)(row & 15) << 4));
                uint32_t r0, r1, r2, r3;
                asm volatile("ldmatrix.sync.aligned.m8n8.x4.trans.shared.b16 {%0,%1,%2,%3}, [%4];"
                             : "=r"(r0), "=r"(r1), "=r"(r2), "=r"(r3)
                             : "r"(bBase + phys));
                b[g * 2][0] = r0; b[g * 2][1] = r1;
                b[g * 2 + 1][0] = r2; b[g * 2 + 1][1] = r3;
            }
        }
#pragma unroll
        for (int mb = 0; mb < 4; mb++)
#pragma unroll
            for (int nb = 0; nb < 8; nb++)
                asm volatile(
                    "mma.sync.aligned.m16n8k16.row.col.f16.f16.f16.f16 "
                    "{%0,%1},{%2,%3,%4,%5},{%6,%7},{%0,%1};"
                    : "+r"(acc[mb][nb][0]), "+r"(acc[mb][nb][1])
                    : "r"(a[mb][0]), "r"(a[mb][1]), "r"(a[mb][2]), "r"(a[mb][3]),
                      "r"(b[nb][0]), "r"(b[nb][1]));
    }
}

// ---------------- GEMM1: y = lk(tok @ npf^T), per-batch tiling (+ npc/ct) ------
// Depth-2 pipeline: two chunks in flight; loads get 2 compute phases of headroom.
__global__ __launch_bounds__(256, 2) void k_mma1() {
    extern __shared__ char smem[];
    uint32_t su = s2u(smem);
    int tid = threadIdx.x, lane = tid & 31, wid = tid >> 5;
    int warpM = wid & 1, warpN = wid >> 1;
    int bx = blockIdx.x, by = blockIdx.y, bz = blockIdx.z;

    const __half *A, *Bp;
    float* CoutF = 0;
    size_t cstr = 0; int M, m0, n0, Nlim = 0, blim; bool isS;
    if (bz < Bn) {
        A = g_tok + (size_t)bz * Ln * Dn;
        Bp = g_npf + (size_t)bx * 256 * Dn;
        M = Ln; m0 = by * 128; n0 = bx * 256; blim = 256; isS = true;
    } else if (by == 0) {
        A = g_img; Bp = g_npf + (size_t)bx * 256 * Dn;
        CoutF = g_npc; cstr = NPn; M = Bn; m0 = 0; n0 = bx * 256;
        Nlim = NPn; blim = 256; isS = false;
    } else if (by == 1 && bx == 0) {
        A = g_img; Bp = g_txt;
        CoutF = g_ct; cstr = Bn; M = Bn; m0 = 0; n0 = 0;
        Nlim = Bn; blim = 128; isS = false;
    } else return;

    uint32_t acc[4][8][2];
#pragma unroll
    for (int i = 0; i < 4; i++)
#pragma unroll
        for (int j = 0; j < 8; j++) { acc[i][j][0] = 0u; acc[i][j][1] = 0u; }

    // prologue: two chunks in flight
#pragma unroll 1
    for (int pre = 0; pre < 2; pre++) {
        uint32_t st = su + (uint32_t)(pre * STAGE_B);
        cpa_tile<128>(st, A, m0, M, (size_t)Dn, pre * 64, tid);
        cpa_tile<256>(st + 16384, Bp, 0, blim, (size_t)Dn, pre * 64, tid);
        CPA_COMMIT();
    }
    for (int it = 0; it < 12; ++it) {
        if (it < 11) asm volatile("cp.async.wait_group 1;" ::: "memory");
        else         asm volatile("cp.async.wait_group 0;" ::: "memory");
        __syncthreads();
        uint32_t base = su + (uint32_t)((it & 1) * STAGE_B);
        mma_compute<false>(base, base + 16384, lane, warpM, warpN, acc);
        if (it + 2 < 12) {
            __syncthreads();   // all warps done reading buf[it&1]
            cpa_tile<128>(base, A, m0, M, (size_t)Dn, (it + 2) * 64, tid);
            cpa_tile<256>(base + 16384, Bp, 0, blim, (size_t)Dn, (it + 2) * 64, tid);
            CPA_COMMIT();
        }
    }
    __syncthreads();

    if (isS) {
        __half* st = (__half*)smem;   // [256][132]
#pragma unroll
        for (int mb = 0; mb < 4; mb++) {
#pragma unroll
            for (int h = 0; h < 2; h++) {
                int ml = warpM * 64 + mb * 16 + (lane >> 2) + h * 8;
                int gr = m0 + ml;
                float ps = 0.f;
#pragma unroll
                for (int nb = 0; nb < 8; nb++) {
                    __half2 hv = *(__half2*)&acc[mb][nb][h];
                    float lx = lk(__half2float(hv.x));
                    float ly = lk(__half2float(hv.y));
                    ps += lx * lx + ly * ly;
                    int nl = warpN * 64 + nb * 8 + (lane & 3) * 2;
                    st[nl * 132 + ml]       = __float2half_rn(lx);
                    st[(nl + 1) * 132 + ml] = __float2half_rn(ly);
                }
                ps += __shfl_xor_sync(0xffffffffu, ps, 1);
                ps += __shfl_xor_sync(0xffffffffu, ps, 2);
                if ((lane & 3) == 0 && gr < M)
                    atomicAdd(&g_norm2[(size_t)bz * Ln + gr], ps);
            }
        }
        __syncthreads();
        // pad columns (l >= 577) may carry garbage y; e=fma(y,0,0)=0 kills them.
#pragma unroll 4
        for (int c = tid; c < 256 * 32; c += 256) {
            int r = c >> 5, ch = c & 31;
            int l = ch * 4;
            __half* dst = g_Yt + ((size_t)bz * NPn + n0 + r) * LP + m0 + l;
            *(uint2*)dst = *(const uint2*)(st + r * 132 + l);
        }
    } else {
#pragma unroll
        for (int mb = 0; mb < 4; mb++) {
#pragma unroll
            for (int h = 0; h < 2; h++) {
                int gr = m0 + warpM * 64 + mb * 16 + (lane >> 2) + h * 8;
                if (gr >= M) continue;
#pragma unroll
                for (int nb = 0; nb < 8; nb++) {
                    int gn = n0 + warpN * 64 + nb * 8 + (lane & 3) * 2;
                    if (gn < Nlim) {
                        __half2 hv = *(__half2*)&acc[mb][nb][h];
                        float2 v;
                        v.x = __half2float(hv.x); v.y = __half2float(hv.y);
                        *(float2*)(CoutF + (size_t)gr * cstr + gn) = v;
                    }
                }
            }
        }
    }
}

// ---------------- GEMM2: e built in-SMEM from y; w_hat = e @ tok ---------------
__global__ __launch_bounds__(256, 2) void k_mma2() {
    extern __shared__ char smem[];
    uint32_t su = s2u(smem);
    int tid = threadIdx.x, lane = tid & 31, wid = tid >> 5;
    int warpM = wid & 1, warpN = wid >> 1;
    int bx = blockIdx.x, by = blockIdx.y, bz = blockIdx.z;

    const __half* A  = g_Yt + (size_t)bz * NPn * LP;
    const __half* Bp = g_tok + (size_t)bz * Ln * Dn + bx * 256;  // pre-offset d0
    int m0 = by * 128;
    bool doNum = (bx == 0);

    // per-l packed (c, a) from g_norm2
    uint32_t* sch = (uint32_t*)(smem + 2 * STAGE_B);
    uint32_t* sca = sch + 320;
    const float* n2b = g_norm2 + (size_t)bz * Ln;
    for (int i = tid; i < 320; i += 256) {
        int l0 = 2 * i, l1 = 2 * i + 1;
        unsigned short c0 = 0, c1 = 0, a0 = 0, a1 = 0;
        if (l0 < Ln) {
            float cf = fminf(rsqrtf(fmaxf(n2b[l0], 1e-16f)) * 5909.2788f, 60000.f);
            c0 = __half_as_ushort(__float2half_rn(cf)); a0 = 0x7380;
        }
        if (l1 < Ln) {
            float cf = fminf(rsqrtf(fmaxf(n2b[l1], 1e-16f)) * 5909.2788f, 60000.f);
            c1 = __half_as_ushort(__float2half_rn(cf)); a1 = 0x7380;
        }
        sch[i] = (uint32_t)c0 | ((uint32_t)c1 << 16);
        sca[i] = (uint32_t)a0 | ((uint32_t)a1 << 16);
    }

    uint32_t acc[4][8][2];
#pragma unroll
    for (int i = 0; i < 4; i++)
#pragma unroll
        for (int j = 0; j < 8; j++) { acc[i][j][0] = 0u; acc[i][j][1] = 0u; }
    float nacc[4] = {0.f, 0.f, 0.f, 0.f};

    cpa_tile<128>(su, A, m0, NPn, (size_t)LP, 0, tid);
    cpa_tile_tr(su + 16384, Bp, 0, Ln, (size_t)Dn, tid);
    CPA_COMMIT();

    const int rR = tid >> 3, cC = tid & 7;
    for (int it = 0; it < 10; ++it) {
        asm volatile("cp.async.wait_group 0;" ::: "memory");
        __syncthreads();
        if (it + 1 < 10) {
            uint32_t nb = su + (uint32_t)(((it + 1) & 1) * STAGE_B);
            cpa_tile<128>(nb, A, m0, NPn, (size_t)LP, (it + 1) * 64, tid);
            cpa_tile_tr(nb + 16384, Bp, (it + 1) * 64, Ln, (size_t)Dn, tid);
            CPA_COMMIT();
        }
        char* bufc = smem + (it & 1) * STAGE_B;
        int sidx = it * 32 + cC * 4;
#pragma unroll
        for (int i = 0; i < 4; i++) {
            int rr = rR + (i << 5);
            uint32_t off = ((uint32_t)(rr << 7)) + ((uint32_t)(cC << 4));
            off ^= (off >> 3) & 0x70;
            uint4 y4 = *(uint4*)(bufc + off);
            uint32_t yv[4] = {y4.x, y4.y, y4.z, y4.w};
            uint32_t ev[4];
#pragma unroll
            for (int j = 0; j < 4; j++) {
                asm("fma.rn.f16x2 %0,%1,%2,%3;"
                    : "=r"(ev[j]) : "r"(yv[j]), "r"(sch[sidx + j]), "r"(sca[sidx + j]));
                if (doNum) {
                    __half2 yh = *(__half2*)&yv[j];
                    __half2 eh = *(__half2*)&ev[j];
                    float a0 = __half2float(yh.x), a1 = __half2float(yh.y);
                    float rw0 = (a0 < 0.f) ? 10.f * a0 : a0;
                    float rw1 = (a1 < 0.f) ? 10.f * a1 : a1;
                    nacc[i] += __half2float(eh.x) * rw0 + __half2float(eh.y) * rw1;
                }
            }
            uint4 e4; e4.x = ev[0]; e4.y = ev[1]; e4.z = ev[2]; e4.w = ev[3];
            *(uint4*)(bufc + off) = e4;
        }
        __syncthreads();
        uint32_t base = su + (uint32_t)((it & 1) * STAGE_B);
        mma_compute<true>(base, base + 16384, lane, warpM, warpN, acc);
    }
    __syncthreads();

    if (doNum) {
#pragma unroll
        for (int i = 0; i < 4; i++) {
            nacc[i] += __shfl_xor_sync(0xffffffffu, nacc[i], 1);
            nacc[i] += __shfl_xor_sync(0xffffffffu, nacc[i], 2);
            nacc[i] += __shfl_xor_sync(0xffffffffu, nacc[i], 4);
        }
        if ((lane & 7) == 0) {
#pragma unroll
            for (int i = 0; i < 4; i++)
                g_num[(size_t)bz * NPn + m0 + rR + (i << 5)] = nacc[i];
        }
    }

#pragma unroll
    for (int mb = 0; mb < 4; mb++) {
#pragma unroll
        for (int h = 0; h < 2; h++) {
            int gr = m0 + warpM * 64 + mb * 16 + (lane >> 2) + h * 8;
            float s = 0.f;
#pragma unroll
            for (int nb = 0; nb < 8; nb++) {
                __half2 hv = *(__half2*)&acc[mb][nb][h];
                float x = __half2float(hv.x), y = __half2float(hv.y);
                s += x * x + y * y;
            }
            s += __shfl_xor_sync(0xffffffffu, s, 1);
            s += __shfl_xor_sync(0xffffffffu, s, 2);
            if ((lane & 3) == 0)
                atomicAdd(&g_wn2[(size_t)bz * NPn + gr], s);
        }
    }
}

// ---------------- fused pre-pass: cvt_tok + cvt_np(+qnorm) + cvt_it + init -----
#define PRE_TOK 27696
#define PRE_NP  (PRE_TOK + NPn)
#define PRE_IT  (PRE_NP + 192)
#define PRE_END (PRE_IT + 512)
__global__ __launch_bounds__(256) void k_pre(const float* __restrict__ npf,
                                             const float* __restrict__ img,
                                             const float* __restrict__ txt,
                                             const float* __restrict__ tok,
                                             const int* __restrict__ idxr) {
    int bb = blockIdx.x, t = threadIdx.x;
    if (bb < PRE_TOK) {
        size_t i = ((size_t)bb * 256 + t) * 8;
        float4 v0 = *(const float4*)(tok + i);
        float4 v1 = *(const float4*)(tok + i + 4);
        __half h[8];
        h[0] = __float2half(v0.x); h[1] = __float2half(v0.y);
        h[2] = __float2half(v0.z); h[3] = __float2half(v0.w);
        h[4] = __float2half(v1.x); h[5] = __float2half(v1.y);
        h[6] = __float2half(v1.z); h[7] = __float2half(v1.w);
        *(uint4*)(g_tok + i) = *(uint4*)h;
    } else if (bb < PRE_NP) {
        int n = bb - PRE_TOK;
        const float* src = npf + (size_t)n * Dn;
        __half* dst = g_npf + (size_t)n * Dn;
        float s = 0.f;
#pragma unroll
        for (int i = 0; i < 3; i++) {
            float v = src[t + i * 256];
            dst[t + i * 256] = __float2half(v);
            s += v * v;
        }
        __shared__ float sh[256];
        sh[t] = s; __syncthreads();
        for (int o = 128; o > 0; o >>= 1) {
            if (t < o) sh[t] += sh[t + o];
            __syncthreads();
        }
        if (t == 0) g_qn[n] = sqrtf(sh[0]);
    } else if (bb < PRE_IT) {
        int i = ((bb - PRE_NP) * 256 + t) * 4;
        const float* src; __half* dst; int off;
        if (i < Bn * Dn)          { src = img; dst = g_img; off = i; }
        else if (i < 2 * Bn * Dn) { src = txt; dst = g_txt; off = i - Bn * Dn; }
        else return;
        float4 v = *(const float4*)(src + off);
        dst[off] = __float2half(v.x); dst[off + 1] = __float2half(v.y);
        dst[off + 2] = __float2half(v.z); dst[off + 3] = __float2half(v.w);
    } else {
        int gid = (bb - PRE_IT) * 256 + t;
        if (gid < Bn * NPn) g_wn2[gid] = 0.f;
        if (gid < Bn * Ln)  g_norm2[gid] = 0.f;
        if (gid == 0) {
            g_acc = 0.f;
            g_lcnt = 0;
            int any = 0;
            for (int i = 1; i < 1024; i += 2) any |= idxr[i];
            g_idx64 = (any == 0) ? 1 : 0;
        }
    }
}
__device__ __forceinline__ int get_idx(const int* __restrict__ r, int n) {
    return g_idx64 ? r[2 * n] : r[n];
}

// ---------------- merged loss reduction + final write ---------------------------
__global__ void k_loss(const float* sc, const float* bi, const int* __restrict__ idxr,
                       float* out) {
    int gid = blockIdx.x * 256 + threadIdx.x;
    float t = 0.f;
    if (gid < Bn * Bn) {
        int i = gid >> 7, j = gid & 127;
        float lg = g_ct[gid] * sc[0] + bi[0];
        float lab = (i == j) ? 1.f : -1.f;
        t = -logsig(lab * lg) * (1.0f / Bn);
    } else if (gid < Bn * Bn + Bn * NPn) {
        int g2 = gid - Bn * Bn;
        int b = g2 >> 10, n = g2 & 1023;
        float lab = (get_idx(idxr, n) == b) ? 1.f : -1.f;
        float lg = g_npc[g2] * sc[0] + bi[0];
        t = -logsig(lab * lg) * (1.0f / NPn);
    } else if (gid < Bn * Bn + 2 * Bn * NPn) {
        int g2 = gid - Bn * Bn - Bn * NPn;
        int b = g2 >> 10, n = g2 & 1023;
        float wn = sqrtf(g_wn2[g2]);
        float den = fmaxf(g_qn[n] * wn, EPSF);
        float sim = g_num[g2] / den;
        float lg = sim * sc[0] + bi[0];
        float lab = (get_idx(idxr, n) == b) ? 1.f : -1.f;
        t = -logsig(lab * lg) * (0.01f / NPn);
    }
    __shared__ float sh[256];
    sh[threadIdx.x] = t; __syncthreads();
    for (int o = 128; o > 0; o >>= 1) {
        if (threadIdx.x < o) sh[threadIdx.x] += sh[threadIdx.x + o];
        __syncthreads();
    }
    if (threadIdx.x == 0) {
        atomicAdd(&g_acc, sh[0]);
        __threadfence();
        int done = atomicAdd(&g_lcnt, 1);
        if (done == (int)gridDim.x - 1)
            out[0] = atomicAdd(&g_acc, 0.f);
    }
}

// ---------------- launch ---------------------------------------------------------
extern "C" void kernel_launch(void* const* d_in, const int* in_sizes, int n_in,
                              void* d_out, int out_size) {
    const float* img = (const float*)d_in[0];
    const float* txt = (const float*)d_in[1];
    const float* sc  = (const float*)d_in[2];
    const float* bi  = (const float*)d_in[3];
    const float* npf = (const float*)d_in[4];
    const int*   idx = (const int*)d_in[5];
    const float* tok = (const float*)d_in[6];
    float* out = (float*)d_out;

    cudaFuncSetAttribute(k_mma1, cudaFuncAttributeMaxDynamicSharedMemorySize, SMEM_MMA1);
    cudaFuncSetAttribute(k_mma2, cudaFuncAttributeMaxDynamicSharedMemorySize, SMEM_MMA2);

    k_pre<<<PRE_END, 256>>>(npf, img, txt, tok, idx);
    k_mma1<<<dim3(4, 5, 129), 256, SMEM_MMA1>>>();
    k_mma2<<<dim3(3, 8, 128), 256, SMEM_MMA2>>>();
    k_loss<<<1088, 256>>>(sc, bi, idx, out);
}

// round 17
// speedup vs baseline: 1.0043x; 1.0043x over previous
#include <cuda_runtime.h>
#include <cuda_fp16.h>
#include <math.h>
#include <stdint.h>

#define Bn  128
#define Ln  577
#define LP  640
#define Dn  768
#define NPn 1024
#define EPSF 1e-8f
#define STAGE_B 49152
#define SMEM_MMA1 (2 * STAGE_B)
#define SMEM_MMA2 (2 * STAGE_B + 2560)

// ---------------- device scratch ----------------
__device__ __half g_Yt [(size_t)Bn*NPn*LP];   // y = leaky(S), [b][n][l]; pads stay 0
__device__ __half g_tok[(size_t)Bn*Ln*Dn];    // tokens fp16, [b][l][d]
__device__ __half g_npf[NPn*Dn];
__device__ __half g_img[Bn*Dn];
__device__ __half g_txt[Bn*Dn];
__device__ float  g_norm2[Bn*Ln];
__device__ float  g_qn  [NPn];
__device__ float  g_num [Bn*NPn];
__device__ float  g_wn2 [Bn*NPn];
__device__ float  g_ct  [Bn*Bn];
__device__ float  g_npc [Bn*NPn];
__device__ float  g_acc;
__device__ int    g_lcnt;
__device__ int    g_idx64;

__device__ __forceinline__ float lk(float x) { return x >= 0.f ? x : 0.1f * x; }
__device__ __forceinline__ float logsig(float x) {
    return fminf(x, 0.f) - log1pf(expf(-fabsf(x)));
}
__device__ __forceinline__ uint32_t s2u(const void* p) {
    uint32_t a;
    asm("{ .reg .u64 t; cvta.to.shared.u64 t, %1; cvt.u32.u64 %0, t; }" : "=r"(a) : "l"(p));
    return a;
}

// -------- cp.async K-major tile: ROWS x 64 halfs, SW128 swizzle ---------------
template<int ROWS>
__device__ __forceinline__ void cpa_tile(uint32_t dst, const __half* __restrict__ src,
                                         int row0, int row_lim, size_t stride, int k0, int tid) {
#pragma unroll
    for (int i = 0; i < ROWS / 32; i++) {
        int e = tid + (i << 8);
        int r = e >> 3, c = e & 7;
        int gr = row0 + r;
        int sz = 16;
        if (gr >= row_lim) { gr = row_lim - 1; sz = 0; }
        const void* gp = (const void*)(src + (size_t)gr * stride + k0 + (c << 3));
        uint32_t off = (uint32_t)((r << 7) + (c << 4));
        off ^= (off >> 3) & 0x70;
        asm volatile("cp.async.cg.shared.global [%0], [%1], 16, %2;"
                     :: "r"(dst + off), "l"(gp), "r"(sz) : "memory");
    }
}
// -------- cp.async MN-major tile: 64 rows(l) x 256 halfs(d), 4-bit row XOR ----
__device__ __forceinline__ void cpa_tile_tr(uint32_t dst, const __half* __restrict__ src,
                                            int row0, int row_lim, size_t stride, int tid) {
#pragma unroll
    for (int i = 0; i < 8; i++) {
        int e = tid + (i << 8);
        int r = e >> 5, c = e & 31;
        int gr = row0 + r;
        int sz = 16;
        if (gr >= row_lim) { gr = row_lim - 1; sz = 0; }
        const void* gp = (const void*)(src + (size_t)gr * stride + (c << 3));
        uint32_t phys = (uint32_t)(r << 9) + ((uint32_t)(c << 4) ^ ((uint32_t)(r & 15) << 4));
        asm volatile("cp.async.cg.shared.global [%0], [%1], 16, %2;"
                     :: "r"(dst + phys), "l"(gp), "r"(sz) : "memory");
    }
}
#define CPA_COMMIT() asm volatile("cp.async.commit_group;" ::: "memory")

// ---------------- warp MMA (f16 acc) over one 128x256x64 SMEM chunk ------------
template<bool TRANSB>
__device__ __forceinline__ void mma_compute(uint32_t aBase, uint32_t bBase,
                                            int lane, int warpM, int warpN,
                                            uint32_t (&acc)[4][8][2]) {
#pragma unroll
    for (int ks = 0; ks < 4; ks++) {
        uint32_t a[4][4];
#pragma unroll
        for (int mb = 0; mb < 4; mb++) {
            int row = warpM * 64 + mb * 16 + (lane & 15);
            uint32_t byte = (uint32_t)(ks * 32 + ((lane >> 4) << 4));
            uint32_t off = (uint32_t)(row << 7) + byte;
            off ^= (off >> 3) & 0x70;
            asm volatile("ldmatrix.sync.aligned.m8n8.x4.shared.b16 {%0,%1,%2,%3}, [%4];"
                         : "=r"(a[mb][0]), "=r"(a[mb][1]), "=r"(a[mb][2]), "=r"(a[mb][3])
                         : "r"(aBase + off));
        }
        uint32_t b[8][2];
        if (!TRANSB) {
#pragma unroll
            for (int g = 0; g < 4; g++) {
                int row = warpN * 64 + g * 16 + (lane & 7) + ((lane >> 4) << 3);
                uint32_t byte = (uint32_t)(ks * 32 + ((lane & 8) ? 16 : 0));
                uint32_t off = (uint32_t)(row << 7) + byte;
                off ^= (off >> 3) & 0x70;
                uint32_t r0, r1, r2, r3;
                asm volatile("ldmatrix.sync.aligned.m8n8.x4.shared.b16 {%0,%1,%2,%3}, [%4];"
                             : "=r"(r0), "=r"(r1), "=r"(r2), "=r"(r3)
                             : "r"(bBase + off));
                b[g * 2][0] = r0; b[g * 2][1] = r1;
                b[g * 2 + 1][0] = r2; b[g * 2 + 1][1] = r3;
            }
        } else {
#pragma unroll
            for (int g = 0; g < 4; g++) {
                int row = ks * 16 + (lane & 15);
                uint32_t bir = (uint32_t)(warpN * 128 + g * 32 + ((lane >> 4) << 4));
                uint32_t phys = (uint32_t)(row << 9) + (bir ^ ((uint32_t)(row & 15) << 4));
                uint32_t r0, r1, r2, r3;
                asm volatile("ldmatrix.sync.aligned.m8n8.x4.trans.shared.b16 {%0,%1,%2,%3}, [%4];"
                             : "=r"(r0), "=r"(r1), "=r"(r2), "=r"(r3)
                             : "r"(bBase + phys));
                b[g * 2][0] = r0; b[g * 2][1] = r1;
                b[g * 2 + 1][0] = r2; b[g * 2 + 1][1] = r3;
            }
        }
#pragma unroll
        for (int mb = 0; mb < 4; mb++)
#pragma unroll
            for (int nb = 0; nb < 8; nb++)
                asm volatile(
                    "mma.sync.aligned.m16n8k16.row.col.f16.f16.f16.f16 "
                    "{%0,%1},{%2,%3,%4,%5},{%6,%7},{%0,%1};"
                    : "+r"(acc[mb][nb][0]), "+r"(acc[mb][nb][1])
                    : "r"(a[mb][0]), "r"(a[mb][1]), "r"(a[mb][2]), "r"(a[mb][3]),
                      "r"(b[nb][0]), "r"(b[nb][1]));
    }
}

// ---------------- GEMM1: y = lk(tok @ npf^T), per-batch tiling (+ npc/ct) ------
__global__ __launch_bounds__(256, 2) void k_mma1() {
    extern __shared__ char smem[];
    uint32_t su = s2u(smem);
    int tid = threadIdx.x, lane = tid & 31, wid = tid >> 5;
    int warpM = wid & 1, warpN = wid >> 1;
    int bx = blockIdx.x, by = blockIdx.y, bz = blockIdx.z;

    const __half *A, *Bp;
    float* CoutF = 0;
    size_t cstr = 0; int M, m0, n0, Nlim = 0, blim; bool isS;
    if (bz < Bn) {
        A = g_tok + (size_t)bz * Ln * Dn;
        Bp = g_npf + (size_t)bx * 256 * Dn;
        M = Ln; m0 = by * 128; n0 = bx * 256; blim = 256; isS = true;
    } else if (by == 0) {
        A = g_img; Bp = g_npf + (size_t)bx * 256 * Dn;
        CoutF = g_npc; cstr = NPn; M = Bn; m0 = 0; n0 = bx * 256;
        Nlim = NPn; blim = 256; isS = false;
    } else if (by == 1 && bx == 0) {
        A = g_img; Bp = g_txt;
        CoutF = g_ct; cstr = Bn; M = Bn; m0 = 0; n0 = 0;
        Nlim = Bn; blim = 128; isS = false;
    } else return;

    uint32_t acc[4][8][2];
#pragma unroll
    for (int i = 0; i < 4; i++)
#pragma unroll
        for (int j = 0; j < 8; j++) { acc[i][j][0] = 0u; acc[i][j][1] = 0u; }

    cpa_tile<128>(su, A, m0, M, (size_t)Dn, 0, tid);
    cpa_tile<256>(su + 16384, Bp, 0, blim, (size_t)Dn, 0, tid);
    CPA_COMMIT();
    for (int it = 0; it < 12; ++it) {
        asm volatile("cp.async.wait_group 0;" ::: "memory");
        __syncthreads();
        if (it + 1 < 12) {
            uint32_t nb = su + (uint32_t)(((it + 1) & 1) * STAGE_B);
            cpa_tile<128>(nb, A, m0, M, (size_t)Dn, (it + 1) * 64, tid);
            cpa_tile<256>(nb + 16384, Bp, 0, blim, (size_t)Dn, (it + 1) * 64, tid);
            CPA_COMMIT();
        }
        uint32_t base = su + (uint32_t)((it & 1) * STAGE_B);
        mma_compute<false>(base, base + 16384, lane, warpM, warpN, acc);
    }
    __syncthreads();

    if (isS) {
        __half* st = (__half*)smem;   // [256][132]
#pragma unroll
        for (int mb = 0; mb < 4; mb++) {
#pragma unroll
            for (int h = 0; h < 2; h++) {
                int ml = warpM * 64 + mb * 16 + (lane >> 2) + h * 8;
                int gr = m0 + ml;
                float ps = 0.f;
#pragma unroll
                for (int nb = 0; nb < 8; nb++) {
                    __half2 hv = *(__half2*)&acc[mb][nb][h];
                    float lx = lk(__half2float(hv.x));
                    float ly = lk(__half2float(hv.y));
                    ps += lx * lx + ly * ly;
                    int nl = warpN * 64 + nb * 8 + (lane & 3) * 2;
                    st[nl * 132 + ml]       = __float2half_rn(lx);
                    st[(nl + 1) * 132 + ml] = __float2half_rn(ly);
                }
                ps += __shfl_xor_sync(0xffffffffu, ps, 1);
                ps += __shfl_xor_sync(0xffffffffu, ps, 2);
                if ((lane & 3) == 0 && gr < M)
                    atomicAdd(&g_norm2[(size_t)bz * Ln + gr], ps);
            }
        }
        __syncthreads();
        // pad columns (l >= 577) may carry garbage y; e=fma(y,0,0)=0 kills them.
#pragma unroll 4
        for (int c = tid; c < 256 * 32; c += 256) {
            int r = c >> 5, ch = c & 31;
            int l = ch * 4;
            __half* dst = g_Yt + ((size_t)bz * NPn + n0 + r) * LP + m0 + l;
            *(uint2*)dst = *(const uint2*)(st + r * 132 + l);
        }
    } else {
#pragma unroll
        for (int mb = 0; mb < 4; mb++) {
#pragma unroll
            for (int h = 0; h < 2; h++) {
                int gr = m0 + warpM * 64 + mb * 16 + (lane >> 2) + h * 8;
                if (gr >= M) continue;
#pragma unroll
                for (int nb = 0; nb < 8; nb++) {
                    int gn = n0 + warpN * 64 + nb * 8 + (lane & 3) * 2;
                    if (gn < Nlim) {
                        __half2 hv = *(__half2*)&acc[mb][nb][h];
                        float2 v;
                        v.x = __half2float(hv.x); v.y = __half2float(hv.y);
                        *(float2*)(CoutF + (size_t)gr * cstr + gn) = v;
                    }
                }
            }
        }
    }
}

// ---------------- GEMM2: e built in-SMEM from y; w_hat = e @ tok ---------------
// e-transform partitioned by warpM half; post-transform sync is a 128-thread
// named barrier per half (consumers of A rows [wm*64, wm*64+64) are exactly the
// 4 warps with warpM==wm), so the two halves don't serialize on each other.
__global__ __launch_bounds__(256, 2) void k_mma2() {
    extern __shared__ char smem[];
    uint32_t su = s2u(smem);
    int tid = threadIdx.x, lane = tid & 31, wid = tid >> 5;
    int warpM = wid & 1, warpN = wid >> 1;
    int bx = blockIdx.x, by = blockIdx.y, bz = blockIdx.z;

    const __half* A  = g_Yt + (size_t)bz * NPn * LP;
    const __half* Bp = g_tok + (size_t)bz * Ln * Dn + bx * 256;  // pre-offset d0
    int m0 = by * 128;
    bool doNum = (bx == 0);

    // per-l packed (c, a) from g_norm2
    uint32_t* sch = (uint32_t*)(smem + 2 * STAGE_B);
    uint32_t* sca = sch + 320;
    const float* n2b = g_norm2 + (size_t)bz * Ln;
    for (int i = tid; i < 320; i += 256) {
        int l0 = 2 * i, l1 = 2 * i + 1;
        unsigned short c0 = 0, c1 = 0, a0 = 0, a1 = 0;
        if (l0 < Ln) {
            float cf = fminf(rsqrtf(fmaxf(n2b[l0], 1e-16f)) * 5909.2788f, 60000.f);
            c0 = __half_as_ushort(__float2half_rn(cf)); a0 = 0x7380;
        }
        if (l1 < Ln) {
            float cf = fminf(rsqrtf(fmaxf(n2b[l1], 1e-16f)) * 5909.2788f, 60000.f);
            c1 = __half_as_ushort(__float2half_rn(cf)); a1 = 0x7380;
        }
        sch[i] = (uint32_t)c0 | ((uint32_t)c1 << 16);
        sca[i] = (uint32_t)a0 | ((uint32_t)a1 << 16);
    }

    uint32_t acc[4][8][2];
#pragma unroll
    for (int i = 0; i < 4; i++)
#pragma unroll
        for (int j = 0; j < 8; j++) { acc[i][j][0] = 0u; acc[i][j][1] = 0u; }
    float nacc[4] = {0.f, 0.f, 0.f, 0.f};

    cpa_tile<128>(su, A, m0, NPn, (size_t)LP, 0, tid);
    cpa_tile_tr(su + 16384, Bp, 0, Ln, (size_t)Dn, tid);
    CPA_COMMIT();

    // group-local transform indexing: 128 threads of half `warpM` own rows
    // [warpM*64, warpM*64+64), 8 16B col-chunks per row, 4 chunks per thread.
    const int tg  = lane + ((wid >> 1) << 5);   // 0..127 within half
    const int rR2 = tg >> 3, cC = tg & 7;
    const int barid = 1 + warpM;
    for (int it = 0; it < 10; ++it) {
        asm volatile("cp.async.wait_group 0;" ::: "memory");
        __syncthreads();
        if (it + 1 < 10) {
            uint32_t nb = su + (uint32_t)(((it + 1) & 1) * STAGE_B);
            cpa_tile<128>(nb, A, m0, NPn, (size_t)LP, (it + 1) * 64, tid);
            cpa_tile_tr(nb + 16384, Bp, (it + 1) * 64, Ln, (size_t)Dn, tid);
            CPA_COMMIT();
        }
        char* bufc = smem + (it & 1) * STAGE_B;
        int sidx = it * 32 + cC * 4;
#pragma unroll
        for (int i = 0; i < 4; i++) {
            int rr = warpM * 64 + rR2 + (i << 4);
            uint32_t off = ((uint32_t)(rr << 7)) + ((uint32_t)(cC << 4));
            off ^= (off >> 3) & 0x70;
            uint4 y4 = *(uint4*)(bufc + off);
            uint32_t yv[4] = {y4.x, y4.y, y4.z, y4.w};
            uint32_t ev[4];
#pragma unroll
            for (int j = 0; j < 4; j++) {
                asm("fma.rn.f16x2 %0,%1,%2,%3;"
                    : "=r"(ev[j]) : "r"(yv[j]), "r"(sch[sidx + j]), "r"(sca[sidx + j]));
                if (doNum) {
                    __half2 yh = *(__half2*)&yv[j];
                    __half2 eh = *(__half2*)&ev[j];
                    float a0 = __half2float(yh.x), a1 = __half2float(yh.y);
                    float rw0 = (a0 < 0.f) ? 10.f * a0 : a0;
                    float rw1 = (a1 < 0.f) ? 10.f * a1 : a1;
                    nacc[i] += __half2float(eh.x) * rw0 + __half2float(eh.y) * rw1;
                }
            }
            uint4 e4; e4.x = ev[0]; e4.y = ev[1]; e4.z = ev[2]; e4.w = ev[3];
            *(uint4*)(bufc + off) = e4;
        }
        asm volatile("bar.sync %0, 128;" :: "r"(barid) : "memory");
        uint32_t base = su + (uint32_t)((it & 1) * STAGE_B);
        mma_compute<true>(base, base + 16384, lane, warpM, warpN, acc);
    }
    __syncthreads();

    if (doNum) {
#pragma unroll
        for (int i = 0; i < 4; i++) {
            nacc[i] += __shfl_xor_sync(0xffffffffu, nacc[i], 1);
            nacc[i] += __shfl_xor_sync(0xffffffffu, nacc[i], 2);
            nacc[i] += __shfl_xor_sync(0xffffffffu, nacc[i], 4);
        }
        if ((lane & 7) == 0) {
            int rbase = m0 + warpM * 64 + ((wid >> 1) << 2) + (lane >> 3);
#pragma unroll
            for (int i = 0; i < 4; i++)
                g_num[(size_t)bz * NPn + rbase + (i << 4)] = nacc[i];
        }
    }

#pragma unroll
    for (int mb = 0; mb < 4; mb++) {
#pragma unroll
        for (int h = 0; h < 2; h++) {
            int gr = m0 + warpM * 64 + mb * 16 + (lane >> 2) + h * 8;
            float s = 0.f;
#pragma unroll
            for (int nb = 0; nb < 8; nb++) {
                __half2 hv = *(__half2*)&acc[mb][nb][h];
                float x = __half2float(hv.x), y = __half2float(hv.y);
                s += x * x + y * y;
            }
            s += __shfl_xor_sync(0xffffffffu, s, 1);
            s += __shfl_xor_sync(0xffffffffu, s, 2);
            if ((lane & 3) == 0)
                atomicAdd(&g_wn2[(size_t)bz * NPn + gr], s);
        }
    }
}

// ---------------- fused pre-pass: cvt_tok + cvt_np(+qnorm) + cvt_it + init -----
#define PRE_TOK 27696
#define PRE_NP  (PRE_TOK + NPn)
#define PRE_IT  (PRE_NP + 192)
#define PRE_END (PRE_IT + 512)
__global__ __launch_bounds__(256) void k_pre(const float* __restrict__ npf,
                                             const float* __restrict__ img,
                                             const float* __restrict__ txt,
                                             const float* __restrict__ tok,
                                             const int* __restrict__ idxr) {
    int bb = blockIdx.x, t = threadIdx.x;
    if (bb < PRE_TOK) {
        size_t i = ((size_t)bb * 256 + t) * 8;
        float4 v0 = *(const float4*)(tok + i);
        float4 v1 = *(const float4*)(tok + i + 4);
        __half h[8];
        h[0] = __float2half(v0.x); h[1] = __float2half(v0.y);
        h[2] = __float2half(v0.z); h[3] = __float2half(v0.w);
        h[4] = __float2half(v1.x); h[5] = __float2half(v1.y);
        h[6] = __float2half(v1.z); h[7] = __float2half(v1.w);
        *(uint4*)(g_tok + i) = *(uint4*)h;
    } else if (bb < PRE_NP) {
        int n = bb - PRE_TOK;
        const float* src = npf + (size_t)n * Dn;
        __half* dst = g_npf + (size_t)n * Dn;
        float s = 0.f;
#pragma unroll
        for (int i = 0; i < 3; i++) {
            float v = src[t + i * 256];
            dst[t + i * 256] = __float2half(v);
            s += v * v;
        }
        __shared__ float sh[256];
        sh[t] = s; __syncthreads();
        for (int o = 128; o > 0; o >>= 1) {
            if (t < o) sh[t] += sh[t + o];
            __syncthreads();
        }
        if (t == 0) g_qn[n] = sqrtf(sh[0]);
    } else if (bb < PRE_IT) {
        int i = ((bb - PRE_NP) * 256 + t) * 4;
        const float* src; __half* dst; int off;
        if (i < Bn * Dn)          { src = img; dst = g_img; off = i; }
        else if (i < 2 * Bn * Dn) { src = txt; dst = g_txt; off = i - Bn * Dn; }
        else return;
        float4 v = *(const float4*)(src + off);
        dst[off] = __float2half(v.x); dst[off + 1] = __float2half(v.y);
        dst[off + 2] = __float2half(v.z); dst[off + 3] = __float2half(v.w);
    } else {
        int gid = (bb - PRE_IT) * 256 + t;
        if (gid < Bn * NPn) g_wn2[gid] = 0.f;
        if (gid < Bn * Ln)  g_norm2[gid] = 0.f;
        if (gid == 0) {
            g_acc = 0.f;
            g_lcnt = 0;
            int any = 0;
            for (int i = 1; i < 1024; i += 2) any |= idxr[i];
            g_idx64 = (any == 0) ? 1 : 0;
        }
    }
}
__device__ __forceinline__ int get_idx(const int* __restrict__ r, int n) {
    return g_idx64 ? r[2 * n] : r[n];
}

// ---------------- merged loss reduction + final write ---------------------------
__global__ void k_loss(const float* sc, const float* bi, const int* __restrict__ idxr,
                       float* out) {
    int gid = blockIdx.x * 256 + threadIdx.x;
    float t = 0.f;
    if (gid < Bn * Bn) {
        int i = gid >> 7, j = gid & 127;
        float lg = g_ct[gid] * sc[0] + bi[0];
        float lab = (i == j) ? 1.f : -1.f;
        t = -logsig(lab * lg) * (1.0f / Bn);
    } else if (gid < Bn * Bn + Bn * NPn) {
        int g2 = gid - Bn * Bn;
        int b = g2 >> 10, n = g2 & 1023;
        float lab = (get_idx(idxr, n) == b) ? 1.f : -1.f;
        float lg = g_npc[g2] * sc[0] + bi[0];
        t = -logsig(lab * lg) * (1.0f / NPn);
    } else if (gid < Bn * Bn + 2 * Bn * NPn) {
        int g2 = gid - Bn * Bn - Bn * NPn;
        int b = g2 >> 10, n = g2 & 1023;
        float wn = sqrtf(g_wn2[g2]);
        float den = fmaxf(g_qn[n] * wn, EPSF);
        float sim = g_num[g2] / den;
        float lg = sim * sc[0] + bi[0];
        float lab = (get_idx(idxr, n) == b) ? 1.f : -1.f;
        t = -logsig(lab * lg) * (0.01f / NPn);
    }
    __shared__ float sh[256];
    sh[threadIdx.x] = t; __syncthreads();
    for (int o = 128; o > 0; o >>= 1) {
        if (threadIdx.x < o) sh[threadIdx.x] += sh[threadIdx.x + o];
        __syncthreads();
    }
    if (threadIdx.x == 0) {
        atomicAdd(&g_acc, sh[0]);
        __threadfence();
        int done = atomicAdd(&g_lcnt, 1);
        if (done == (int)gridDim.x - 1)
            out[0] = atomicAdd(&g_acc, 0.f);
    }
}

// ---------------- launch ---------------------------------------------------------
extern "C" void kernel_launch(void* const* d_in, const int* in_sizes, int n_in,
                              void* d_out, int out_size) {
    const float* img = (const float*)d_in[0];
    const float* txt = (const float*)d_in[1];
    const float* sc  = (const float*)d_in[2];
    const float* bi  = (const float*)d_in[3];
    const float* npf = (const float*)d_in[4];
    const int*   idx = (const int*)d_in[5];
    const float* tok = (const float*)d_in[6];
    float* out = (float*)d_out;

    cudaFuncSetAttribute(k_mma1, cudaFuncAttributeMaxDynamicSharedMemorySize, SMEM_MMA1);
    cudaFuncSetAttribute(k_mma2, cudaFuncAttributeMaxDynamicSharedMemorySize, SMEM_MMA2);

    k_pre<<<PRE_END, 256>>>(npf, img, txt, tok, idx);
    k_mma1<<<dim3(4, 5, 129), 256, SMEM_MMA1>>>();
    k_mma2<<<dim3(3, 8, 128), 256, SMEM_MMA2>>>();
    k_loss<<<1088, 256>>>(sc, bi, idx, out);
}